// round 12
// baseline (speedup 1.0000x reference)
#include <cuda_runtime.h>
#include <cuda_fp16.h>
#include <math.h>
#include <cstdint>

#define BATCH 8
#define LSEQ  4096
#define DMODEL 256
#define NHEAD 8
#define DHEAD 32
#define MROWS (BATCH*LSEQ)
#define NUM_LAYERS 4
#define QKVN (3*DMODEL)   // 768

// ---------------- helpers ----------------
__device__ __forceinline__ uint32_t smem_u32(const void* p) {
    uint32_t a;
    asm("{ .reg .u64 t; cvta.to.shared.u64 t, %1; cvt.u32.u64 %0, t; }" : "=r"(a) : "l"(p));
    return a;
}
__device__ __forceinline__ void cpa(uint32_t s, const void* g) {
    asm volatile("cp.async.cg.shared.global [%0], [%1], 16;" :: "r"(s), "l"(g));
}
__device__ __forceinline__ void cpa_commit() { asm volatile("cp.async.commit_group;" ::: "memory"); }
#define CPA_WAIT(n) asm volatile("cp.async.wait_group %0;" :: "n"(n) : "memory")
__device__ __forceinline__ void ldm_x4(uint32_t* r, uint32_t a) {
    asm volatile("ldmatrix.sync.aligned.m8n8.x4.shared.b16 {%0,%1,%2,%3}, [%4];"
        : "=r"(r[0]), "=r"(r[1]), "=r"(r[2]), "=r"(r[3]) : "r"(a));
}
#define MMA(c, a, b0v, b1v) \
    asm volatile("mma.sync.aligned.m16n8k16.row.col.f32.f16.f16.f32 " \
        "{%0,%1,%2,%3}, {%4,%5,%6,%7}, {%8,%9}, {%0,%1,%2,%3};" \
        : "+f"((c)[0]), "+f"((c)[1]), "+f"((c)[2]), "+f"((c)[3]) \
        : "r"((a)[0]), "r"((a)[1]), "r"((a)[2]), "r"((a)[3]), "r"(b0v), "r"(b1v))
__device__ __forceinline__ float warp_sum(float v) {
    #pragma unroll
    for (int o = 16; o > 0; o >>= 1) v += __shfl_xor_sync(0xffffffffu, v, o);
    return v;
}

// ---------------- scratch ----------------
__device__ float g_x[MROWS * DMODEL];
__device__ float g_kvp[BATCH * NHEAD * 8 * (DHEAD * DHEAD + DHEAD)];
__device__ __half g_qkv[MROWS * QKVN];               // fp16 [Q|K|V]
__device__ __half g_xh[MROWS * DMODEL];              // fp16(x)
__device__ __half g_msgh[MROWS * DMODEL];            // fp16(msg)
__device__ __half g_lnh[MROWS * DMODEL];             // fp16(LN(merged))
__device__ __half g_h1h[MROWS * 2 * DMODEL];         // fp16(relu(mlp1))
__device__ __half g_wh[NUM_LAYERS * 10 * DMODEL * DMODEL];  // weights fp16 [N][K]
#define WSZ_D (DMODEL * DMODEL)
#define WSZ_L (10 * WSZ_D)
#define OFF_Q 0
#define OFF_K (1 * WSZ_D)
#define OFF_V (2 * WSZ_D)
#define OFF_M (3 * WSZ_D)
#define OFF_1 (4 * WSZ_D)
#define OFF_2 (8 * WSZ_D)

// ---------------- PE + transposes ----------------
__device__ __forceinline__ float pe_val(int c, int l) {
    int i = c >> 2, m = c & 3;
    float pos = (m < 2) ? (float)((l & 63) + 1) : (float)((l >> 6) + 1);
    float dv = expf(-(float)(2 * i) * 0.07195578490697396f);
    float a = pos * dv;
    return (m & 1) ? cosf(a) : sinf(a);
}
__global__ void add_pe_transpose(const float* __restrict__ feats) {
    __shared__ float t[32][33];
    int b = blockIdx.z, c0 = blockIdx.y * 32, l0 = blockIdx.x * 32;
    int tx = threadIdx.x, ty = threadIdx.y;
    #pragma unroll
    for (int i = ty; i < 32; i += 8) {
        int c = c0 + i, l = l0 + tx;
        t[i][tx] = feats[((size_t)b * DMODEL + c) * LSEQ + l] + pe_val(c, l);
    }
    __syncthreads();
    #pragma unroll
    for (int i = ty; i < 32; i += 8) {
        int l = l0 + i, c = c0 + tx;
        float v = t[tx][i];
        size_t o = ((size_t)b * LSEQ + l) * DMODEL + c;
        g_x[o] = v;
        g_xh[o] = __float2half_rn(v);
    }
}
__global__ void transpose_out(float* __restrict__ out) {
    __shared__ float t[32][33];
    int b = blockIdx.z, c0 = blockIdx.y * 32, l0 = blockIdx.x * 32;
    int tx = threadIdx.x, ty = threadIdx.y;
    #pragma unroll
    for (int i = ty; i < 32; i += 8)
        t[i][tx] = g_x[((size_t)b * LSEQ + l0 + i) * DMODEL + c0 + tx];
    __syncthreads();
    #pragma unroll
    for (int i = ty; i < 32; i += 8)
        out[((size_t)b * DMODEL + c0 + i) * LSEQ + l0 + tx] = t[tx][i];
}

// W[K][N] fp32 -> [N][K] fp16 (transpose + round)
__global__ void prep_weight(const float* __restrict__ W, __half* __restrict__ Th,
                            int K, int N, int wstride, int ostride) {
    __shared__ float t[32][33];
    int L = blockIdx.z;
    const float* Wp = W + (size_t)L * wstride;
    int k0 = blockIdx.y * 32, n0 = blockIdx.x * 32;
    int tx = threadIdx.x, ty = threadIdx.y;
    #pragma unroll
    for (int i = ty; i < 32; i += 8)
        t[i][tx] = Wp[(size_t)(k0 + i) * N + n0 + tx];
    __syncthreads();
    #pragma unroll
    for (int i = ty; i < 32; i += 8) {
        float v = t[tx][i];
        size_t o = (size_t)L * ostride + (size_t)(n0 + i) * K + k0 + tx;
        Th[o] = __float2half_rn(v);
    }
}

// ---------------- mma.sync fp16 GEMM, CTA 128x256, 512 thr ----------------
// C = A @ B^T. A fp16 [M][K]; B fp16 [N][K]. 16 warps (2m x 8n), warp 64x32,
// BK=64, 3-stage ring, one barrier per chunk.
// DUALA: A cols [0,256) from A, [256,512) from A2, both stride 256.
// EPI: 2 relu+fp16, 3 qkv fp16 (elu+1 if col<512),
//      4 row-LN -> fp16 (g_lnh), 5 row-LN + residual into g_x / g_xh
#define BM 128
#define BN 256
#define BK 64
#define ATILE 16384                   // 128x64 fp16
#define BTILE 32768                   // 256x64 fp16
#define STG (ATILE + BTILE)           // 49152
#define NSTAGE 3
#define GSMEM (NSTAGE * STG)          // 147456 >= 128*264*4 epilogue tile

template <int EPI, bool DUALA>
__global__ __launch_bounds__(512, 1) void mmagemm(
    const __half* __restrict__ A, const __half* __restrict__ A2,
    const __half* __restrict__ B,
    __half* __restrict__ Ch,
    const float* __restrict__ gam, const float* __restrict__ bet,
    int Ndim, int Kdim)
{
    extern __shared__ char sraw[];
    const uint32_t sbase = smem_u32(sraw);

    const int tid = threadIdx.x;
    const int bm0 = blockIdx.y * BM, bn0 = blockIdx.x * BN;
    const int lane = tid & 31, warp = tid >> 5;
    const int wm = warp >> 3, wn = warp & 7;   // 2 x 8 warp grid

    const int lrow = tid >> 3;            // 0..63
    const int lc16 = tid & 7;

    // ldmatrix bases
    uint32_t aRB[4]; int aR3[4];
    const int khA = lane >> 4;
    #pragma unroll
    for (int mt = 0; mt < 4; mt++) {
        int row = wm * 64 + mt * 16 + (lane & 15);
        aRB[mt] = sbase + row * 128;
        aR3[mt] = row & 7;
    }
    uint32_t bRB[2]; int bR3[2];
    const int khB = (lane >> 3) & 1;
    #pragma unroll
    for (int g = 0; g < 2; g++) {
        int row = wn * 32 + g * 16 + ((lane >> 4) & 1) * 8 + (lane & 7);
        bRB[g] = sbase + ATILE + row * 128;
        bR3[g] = row & 7;
    }

    float acc[4][4][4];
    #pragma unroll
    for (int i = 0; i < 4; i++)
        #pragma unroll
        for (int j = 0; j < 4; j++)
            #pragma unroll
            for (int e = 0; e < 4; e++) acc[i][j][e] = 0.f;

    const int nk = Kdim / BK;

    auto load_stage = [&](int st, int kblk) {
        uint32_t sb = sbase + (uint32_t)st * STG;
        const __half* pA;
        int acol, astr;
        if (DUALA && kblk >= DMODEL) {
            pA = A2; acol = kblk - DMODEL; astr = DMODEL;
        } else {
            pA = A; acol = kblk; astr = DUALA ? DMODEL : Kdim;
        }
        #pragma unroll
        for (int i = 0; i < 2; i++) {        // A: 128 rows
            int row = lrow + i * 64;
            uint32_t so = (uint32_t)(row * 128 + ((lc16 ^ (row & 7)) << 4));
            size_t gA = (size_t)(bm0 + row) * astr + acol + lc16 * 8;
            cpa(sb + so, pA + gA);
        }
        #pragma unroll
        for (int i = 0; i < 4; i++) {        // B: 256 rows
            int row = lrow + i * 64;
            uint32_t so = (uint32_t)(row * 128 + ((lc16 ^ (row & 7)) << 4));
            size_t gB = (size_t)(bn0 + row) * Kdim + kblk + lc16 * 8;
            cpa(sb + ATILE + so, B + gB);
        }
        cpa_commit();
    };

    load_stage(0, 0);
    load_stage(1, BK);

    for (int c = 0; c < nk; c++) {
        CPA_WAIT(NSTAGE - 2);
        __syncthreads();
        if (c + 2 < nk) load_stage((c + 2) % NSTAGE, (c + 2) * BK);
        else cpa_commit();

        uint32_t soff = (uint32_t)(c % NSTAGE) * STG;
        #pragma unroll
        for (int s = 0; s < 4; s++) {        // four k16 slabs in BK=64
            uint32_t a[4][4], bh[2][4];
            #pragma unroll
            for (int mt = 0; mt < 4; mt++)
                ldm_x4(a[mt], aRB[mt] + soff + (uint32_t)(((s * 2 + khA) ^ aR3[mt]) << 4));
            #pragma unroll
            for (int g = 0; g < 2; g++)
                ldm_x4(bh[g], bRB[g] + soff + (uint32_t)(((s * 2 + khB) ^ bR3[g]) << 4));
            #pragma unroll
            for (int mt = 0; mt < 4; mt++)
                #pragma unroll
                for (int nt = 0; nt < 4; nt++)
                    MMA(acc[mt][nt], a[mt], bh[nt >> 1][(nt & 1) * 2], bh[nt >> 1][(nt & 1) * 2 + 1]);
        }
    }

    if (EPI == 2 || EPI == 3) {
        const bool qkv_act = (EPI == 3) && (bn0 < 2 * DMODEL);
        #pragma unroll
        for (int mt = 0; mt < 4; mt++) {
            #pragma unroll
            for (int nt = 0; nt < 4; nt++) {
                int row = bm0 + wm * 64 + mt * 16 + (lane >> 2);
                int col = bn0 + wn * 32 + nt * 8 + (lane & 3) * 2;
                float* a = acc[mt][nt];
                #pragma unroll
                for (int half = 0; half < 2; half++) {
                    int r = row + half * 8;
                    float v0 = a[half * 2], v1 = a[half * 2 + 1];
                    size_t o = (size_t)r * Ndim + col;
                    if (EPI == 3) {
                        if (qkv_act) {
                            v0 = v0 > 0.f ? v0 + 1.f : expf(v0);
                            v1 = v1 > 0.f ? v1 + 1.f : expf(v1);
                        }
                    } else {
                        v0 = v0 > 0.f ? v0 : 0.f;
                        v1 = v1 > 0.f ? v1 : 0.f;
                    }
                    __half2 p;
                    p.x = __float2half_rn(v0);
                    p.y = __float2half_rn(v1);
                    *(__half2*)(Ch + o) = p;
                }
            }
        }
    } else {
        // EPI 4/5: stage fp32 C tile in smem, per-row LayerNorm
        __syncthreads();                       // pipeline stages now dead
        float* sC = (float*)sraw;              // [128][264]
        #pragma unroll
        for (int mt = 0; mt < 4; mt++) {
            #pragma unroll
            for (int nt = 0; nt < 4; nt++) {
                int rl = wm * 64 + mt * 16 + (lane >> 2);
                int cl = wn * 32 + nt * 8 + (lane & 3) * 2;
                float* a = acc[mt][nt];
                #pragma unroll
                for (int half = 0; half < 2; half++) {
                    int r = rl + half * 8;
                    sC[r * 264 + cl] = a[half * 2];
                    sC[r * 264 + cl + 1] = a[half * 2 + 1];
                }
            }
        }
        __syncthreads();
        // each warp: 8 rows
        #pragma unroll
        for (int rr = 0; rr < 8; rr++) {
            int rl = warp * 8 + rr;
            int grow = bm0 + rl;
            float v[8]; float s = 0.f;
            #pragma unroll
            for (int j = 0; j < 8; j++) { v[j] = sC[rl * 264 + lane + 32 * j]; s += v[j]; }
            s = warp_sum(s);
            float mu = s * (1.f / 256.f), s2 = 0.f;
            #pragma unroll
            for (int j = 0; j < 8; j++) { float d = v[j] - mu; s2 += d * d; }
            s2 = warp_sum(s2);
            float rs = rsqrtf(s2 * (1.f / 256.f) + 1e-5f);
            #pragma unroll
            for (int j = 0; j < 8; j++) {
                int cidx = lane + 32 * j;
                float lnv = (v[j] - mu) * rs * gam[cidx] + bet[cidx];
                size_t o = (size_t)grow * DMODEL + cidx;
                if (EPI == 4) {
                    g_lnh[o] = __float2half_rn(lnv);
                } else {
                    float nx = g_x[o] + lnv;
                    g_x[o] = nx;
                    g_xh[o] = __float2half_rn(nx);
                }
            }
        }
    }
}

// ---------------- KV reduce phase 1 (32-row tiles, fp16 in) ----------------
__global__ __launch_bounds__(256) void kv_reduce1() {
    int blk = blockIdx.x;
    int sl = blk & 7, nh = blk >> 3;
    int n = nh >> 3, h = nh & 7;
    const __half* Kp = g_qkv + (size_t)n * LSEQ * QKVN + DMODEL + h * DHEAD;
    const __half* Vp = Kp + DMODEL;
    __shared__ float sK[32][32], sV[32][32];
    int tid = threadIdx.x;
    int d0 = tid >> 3, v0 = (tid & 7) * 4;
    int lrow = tid >> 3, lcol = (tid & 7) * 4;
    float a0 = 0, a1 = 0, a2 = 0, a3 = 0, ks = 0;
    int lbeg = sl * 512, lend = lbeg + 512;
    for (int l0 = lbeg; l0 < lend; l0 += 32) {
        size_t ro = (size_t)(l0 + lrow) * QKVN + lcol;
        {
            uint2 rk = *(const uint2*)(Kp + ro);
            float2 k01 = __half22float2(*(__half2*)&rk.x);
            float2 k23 = __half22float2(*(__half2*)&rk.y);
            sK[lrow][lcol + 0] = k01.x; sK[lrow][lcol + 1] = k01.y;
            sK[lrow][lcol + 2] = k23.x; sK[lrow][lcol + 3] = k23.y;
            uint2 rv = *(const uint2*)(Vp + ro);
            float2 v01 = __half22float2(*(__half2*)&rv.x);
            float2 v23 = __half22float2(*(__half2*)&rv.y);
            sV[lrow][lcol + 0] = v01.x; sV[lrow][lcol + 1] = v01.y;
            sV[lrow][lcol + 2] = v23.x; sV[lrow][lcol + 3] = v23.y;
        }
        __syncthreads();
        #pragma unroll
        for (int r = 0; r < 32; r++) {
            float kd = sK[r][d0];
            a0 += kd * sV[r][v0 + 0];
            a1 += kd * sV[r][v0 + 1];
            a2 += kd * sV[r][v0 + 2];
            a3 += kd * sV[r][v0 + 3];
            if ((tid & 7) == 0) ks += kd;
        }
        __syncthreads();
    }
    float* p = g_kvp + (size_t)blk * (DHEAD * DHEAD + DHEAD);
    float* kv = p + d0 * DHEAD + v0;
    kv[0] = a0; kv[1] = a1; kv[2] = a2; kv[3] = a3;
    if ((tid & 7) == 0) p[DHEAD * DHEAD + d0] = ks;
}

// ---------------- attention apply (reduces partials itself) ----------------
__global__ __launch_bounds__(256) void attn_apply() {
    int n = blockIdx.y, l0 = blockIdx.x * 128;
    __shared__ float sKV[NHEAD][DHEAD][DHEAD];
    __shared__ float sKs[NHEAD][DHEAD];
    int tid = threadIdx.x;
    const int PSTR = DHEAD * DHEAD + DHEAD;   // 1056
    const float* base = g_kvp + (size_t)n * NHEAD * 8 * PSTR;
    for (int i = tid; i < NHEAD * DHEAD * DHEAD; i += 256) {
        int h = i >> 10, e = i & 1023;
        float s = 0.f;
        #pragma unroll
        for (int p = 0; p < 8; p++) s += base[(size_t)(h * 8 + p) * PSTR + e];
        ((float*)sKV)[i] = s;
    }
    for (int i = tid; i < NHEAD * DHEAD; i += 256) {
        int h = i >> 5, e = i & 31;
        float s = 0.f;
        #pragma unroll
        for (int p = 0; p < 8; p++) s += base[(size_t)(h * 8 + p) * PSTR + 1024 + e];
        ((float*)sKs)[i] = s;
    }
    __syncthreads();
    #pragma unroll
    for (int p = 0; p < 4; p++) {
        int i = p * 256 + tid;
        int h = i >> 7, ll = i & 127;
        const __half* qp = g_qkv + ((size_t)n * LSEQ + l0 + ll) * QKVN + h * DHEAD;
        size_t rowo = ((size_t)n * LSEQ + l0 + ll) * DMODEL + h * DHEAD;
        float q[32];
        #pragma unroll
        for (int d = 0; d < 32; d += 8) {
            uint2 rq = *(const uint2*)(qp + d);
            float2 q01 = __half22float2(*(__half2*)&rq.x);
            float2 q23 = __half22float2(*(__half2*)&rq.y);
            q[d + 0] = q01.x; q[d + 1] = q01.y; q[d + 2] = q23.x; q[d + 3] = q23.y;
            uint2 rq2 = *(const uint2*)(qp + d + 4);
            float2 q45 = __half22float2(*(__half2*)&rq2.x);
            float2 q67 = __half22float2(*(__half2*)&rq2.y);
            q[d + 4] = q45.x; q[d + 5] = q45.y; q[d + 6] = q67.x; q[d + 7] = q67.y;
        }
        float zdot = 0.f;
        #pragma unroll
        for (int d = 0; d < 32; d++) zdot += q[d] * sKs[h][d];
        float z = 1.f / (zdot + 1e-6f);
        #pragma unroll
        for (int v = 0; v < 32; v += 2) {
            float b0 = 0.f, b1 = 0.f;
            #pragma unroll
            for (int d = 0; d < 32; d++) {
                float qq = q[d];
                b0 += qq * sKV[h][d][v];
                b1 += qq * sKV[h][d][v + 1];
            }
            __half2 ph;
            ph.x = __float2half_rn(b0 * z);
            ph.y = __float2half_rn(b1 * z);
            *(__half2*)(g_msgh + rowo + v) = ph;
        }
    }
}

// ---------------- host ----------------
extern "C" void kernel_launch(void* const* d_in, const int* in_sizes, int n_in,
                              void* d_out, int out_size)
{
    const float* feats = (const float*)d_in[0];
    const float* Wq = (const float*)d_in[1];
    const float* Wk = (const float*)d_in[2];
    const float* Wv = (const float*)d_in[3];
    const float* Wm = (const float*)d_in[4];
    const float* W1 = (const float*)d_in[5];
    const float* W2 = (const float*)d_in[6];
    const float* ln1g = (const float*)d_in[7];
    const float* ln1b = (const float*)d_in[8];
    const float* ln2g = (const float*)d_in[9];
    const float* ln2b = (const float*)d_in[10];

    cudaFuncSetAttribute(mmagemm<2, true>,  cudaFuncAttributeMaxDynamicSharedMemorySize, GSMEM);
    cudaFuncSetAttribute(mmagemm<3, false>, cudaFuncAttributeMaxDynamicSharedMemorySize, GSMEM);
    cudaFuncSetAttribute(mmagemm<4, false>, cudaFuncAttributeMaxDynamicSharedMemorySize, GSMEM);
    cudaFuncSetAttribute(mmagemm<5, false>, cudaFuncAttributeMaxDynamicSharedMemorySize, GSMEM);

    __half *pqkv, *pxh, *pmh, *plh, *p1h, *pwh;
    cudaGetSymbolAddress((void**)&pqkv, g_qkv);
    cudaGetSymbolAddress((void**)&pxh, g_xh);
    cudaGetSymbolAddress((void**)&pmh, g_msgh);
    cudaGetSymbolAddress((void**)&plh, g_lnh);
    cudaGetSymbolAddress((void**)&p1h, g_h1h);
    cudaGetSymbolAddress((void**)&pwh, g_wh);

    dim3 tb(32, 8);
    prep_weight<<<dim3(8, 8, NUM_LAYERS), tb>>>(Wq, pwh + OFF_Q, DMODEL, DMODEL, WSZ_D, WSZ_L);
    prep_weight<<<dim3(8, 8, NUM_LAYERS), tb>>>(Wk, pwh + OFF_K, DMODEL, DMODEL, WSZ_D, WSZ_L);
    prep_weight<<<dim3(8, 8, NUM_LAYERS), tb>>>(Wv, pwh + OFF_V, DMODEL, DMODEL, WSZ_D, WSZ_L);
    prep_weight<<<dim3(8, 8, NUM_LAYERS), tb>>>(Wm, pwh + OFF_M, DMODEL, DMODEL, WSZ_D, WSZ_L);
    prep_weight<<<dim3(16, 16, NUM_LAYERS), tb>>>(W1, pwh + OFF_1, 2 * DMODEL, 2 * DMODEL, 4 * WSZ_D, WSZ_L);
    prep_weight<<<dim3(8, 16, NUM_LAYERS), tb>>>(W2, pwh + OFF_2, 2 * DMODEL, DMODEL, 2 * WSZ_D, WSZ_L);

    add_pe_transpose<<<dim3(LSEQ / 32, DMODEL / 32, BATCH), tb>>>(feats);

    dim3 blk(512);
    dim3 grid_qkv(QKVN / BN, MROWS / BM);       // (3, 256)
    dim3 grid_d(1, MROWS / BM);                 // (1, 256)
    dim3 grid_2d(2 * DMODEL / BN, MROWS / BM);  // (2, 256)

    for (int i = 0; i < NUM_LAYERS; i++) {
        size_t wo = (size_t)i * WSZ_L;
        // fused QKV -> fp16 [elu(x@Wq)+1 | elu(x@Wk)+1 | x@Wv]
        mmagemm<3, false><<<grid_qkv, blk, GSMEM>>>(pxh, 0, pwh + wo + OFF_Q, pqkv, 0, 0, QKVN, DMODEL);

        kv_reduce1<<<BATCH * NHEAD * 8, 256>>>();
        attn_apply<<<dim3(LSEQ / 128, BATCH), 256>>>();

        // merged = msg @ Wm, fused LN1 -> g_lnh fp16
        mmagemm<4, false><<<grid_d, blk, GSMEM>>>(pmh, 0, pwh + wo + OFF_M, 0,
                                                  ln1g + i * DMODEL, ln1b + i * DMODEL, DMODEL, DMODEL);

        // h1 = relu([x | LN] @ W1) -> fp16
        mmagemm<2, true><<<grid_2d, blk, GSMEM>>>(pxh, plh, pwh + wo + OFF_1, p1h, 0, 0, 2 * DMODEL, 2 * DMODEL);
        // h2 = h1 @ W2, fused LN2 + residual -> g_x / g_xh
        mmagemm<5, false><<<grid_d, blk, GSMEM>>>(p1h, 0, pwh + wo + OFF_2, 0,
                                                  ln2g + i * DMODEL, ln2b + i * DMODEL, DMODEL, 2 * DMODEL);
    }

    transpose_out<<<dim3(LSEQ / 32, DMODEL / 32, BATCH), tb>>>((float*)d_out);
}

// round 13
// speedup vs baseline: 1.1489x; 1.1489x over previous
#include <cuda_runtime.h>
#include <cuda_fp16.h>
#include <math.h>
#include <cstdint>

#define BATCH 8
#define LSEQ  4096
#define DMODEL 256
#define NHEAD 8
#define DHEAD 32
#define MROWS (BATCH*LSEQ)
#define NUM_LAYERS 4
#define QKVN (3*DMODEL)   // 768

// ---------------- helpers ----------------
__device__ __forceinline__ uint32_t smem_u32(const void* p) {
    uint32_t a;
    asm("{ .reg .u64 t; cvta.to.shared.u64 t, %1; cvt.u32.u64 %0, t; }" : "=r"(a) : "l"(p));
    return a;
}
__device__ __forceinline__ void cpa(uint32_t s, const void* g) {
    asm volatile("cp.async.cg.shared.global [%0], [%1], 16;" :: "r"(s), "l"(g));
}
__device__ __forceinline__ void cpa_commit() { asm volatile("cp.async.commit_group;" ::: "memory"); }
#define CPA_WAIT(n) asm volatile("cp.async.wait_group %0;" :: "n"(n) : "memory")
__device__ __forceinline__ void ldm_x4(uint32_t* r, uint32_t a) {
    asm volatile("ldmatrix.sync.aligned.m8n8.x4.shared.b16 {%0,%1,%2,%3}, [%4];"
        : "=r"(r[0]), "=r"(r[1]), "=r"(r[2]), "=r"(r[3]) : "r"(a));
}
#define MMA(c, a, b0v, b1v) \
    asm volatile("mma.sync.aligned.m16n8k16.row.col.f32.f16.f16.f32 " \
        "{%0,%1,%2,%3}, {%4,%5,%6,%7}, {%8,%9}, {%0,%1,%2,%3};" \
        : "+f"((c)[0]), "+f"((c)[1]), "+f"((c)[2]), "+f"((c)[3]) \
        : "r"((a)[0]), "r"((a)[1]), "r"((a)[2]), "r"((a)[3]), "r"(b0v), "r"(b1v))
__device__ __forceinline__ float warp_sum(float v) {
    #pragma unroll
    for (int o = 16; o > 0; o >>= 1) v += __shfl_xor_sync(0xffffffffu, v, o);
    return v;
}

// ---------------- scratch ----------------
__device__ float g_x[MROWS * DMODEL];
__device__ float g_tmp[MROWS * DMODEL];
__device__ float g_kvp[BATCH * NHEAD * 8 * (DHEAD * DHEAD + DHEAD)];
__device__ __half g_qkv[MROWS * QKVN];               // fp16 [Q|K|V]
__device__ __half g_xh[MROWS * DMODEL];              // fp16(x)
__device__ __half g_msgh[MROWS * DMODEL];            // fp16(msg)
__device__ __half g_lnh[MROWS * DMODEL];             // fp16(LN(merged))
__device__ __half g_h1h[MROWS * 2 * DMODEL];         // fp16(relu(mlp1))
__device__ __half g_wh[NUM_LAYERS * 10 * DMODEL * DMODEL];  // weights fp16 [N][K]
#define WSZ_D (DMODEL * DMODEL)
#define WSZ_L (10 * WSZ_D)
#define OFF_Q 0
#define OFF_K (1 * WSZ_D)
#define OFF_V (2 * WSZ_D)
#define OFF_M (3 * WSZ_D)
#define OFF_1 (4 * WSZ_D)
#define OFF_2 (8 * WSZ_D)

// ---------------- PE + transposes ----------------
__device__ __forceinline__ float pe_val(int c, int l) {
    int i = c >> 2, m = c & 3;
    float pos = (m < 2) ? (float)((l & 63) + 1) : (float)((l >> 6) + 1);
    float dv = expf(-(float)(2 * i) * 0.07195578490697396f);
    float a = pos * dv;
    return (m & 1) ? cosf(a) : sinf(a);
}
__global__ void add_pe_transpose(const float* __restrict__ feats) {
    __shared__ float t[32][33];
    int b = blockIdx.z, c0 = blockIdx.y * 32, l0 = blockIdx.x * 32;
    int tx = threadIdx.x, ty = threadIdx.y;
    #pragma unroll
    for (int i = ty; i < 32; i += 8) {
        int c = c0 + i, l = l0 + tx;
        t[i][tx] = feats[((size_t)b * DMODEL + c) * LSEQ + l] + pe_val(c, l);
    }
    __syncthreads();
    #pragma unroll
    for (int i = ty; i < 32; i += 8) {
        int l = l0 + i, c = c0 + tx;
        float v = t[tx][i];
        size_t o = ((size_t)b * LSEQ + l) * DMODEL + c;
        g_x[o] = v;
        g_xh[o] = __float2half_rn(v);
    }
}
__global__ void transpose_out(float* __restrict__ out) {
    __shared__ float t[32][33];
    int b = blockIdx.z, c0 = blockIdx.y * 32, l0 = blockIdx.x * 32;
    int tx = threadIdx.x, ty = threadIdx.y;
    #pragma unroll
    for (int i = ty; i < 32; i += 8)
        t[i][tx] = g_x[((size_t)b * LSEQ + l0 + i) * DMODEL + c0 + tx];
    __syncthreads();
    #pragma unroll
    for (int i = ty; i < 32; i += 8)
        out[((size_t)b * DMODEL + c0 + i) * LSEQ + l0 + tx] = t[tx][i];
}

// W[K][N] fp32 -> [N][K] fp16 (transpose + round)
__global__ void prep_weight(const float* __restrict__ W, __half* __restrict__ Th,
                            int K, int N, int wstride, int ostride) {
    __shared__ float t[32][33];
    int L = blockIdx.z;
    const float* Wp = W + (size_t)L * wstride;
    int k0 = blockIdx.y * 32, n0 = blockIdx.x * 32;
    int tx = threadIdx.x, ty = threadIdx.y;
    #pragma unroll
    for (int i = ty; i < 32; i += 8)
        t[i][tx] = Wp[(size_t)(k0 + i) * N + n0 + tx];
    __syncthreads();
    #pragma unroll
    for (int i = ty; i < 32; i += 8) {
        float v = t[tx][i];
        size_t o = (size_t)L * ostride + (size_t)(n0 + i) * K + k0 + tx;
        Th[o] = __float2half_rn(v);
    }
}

// ---------------- mma.sync fp16 1-pass GEMM ----------------
// C = A @ B^T. A fp16 [M][K]; B fp16 [N][K].
// CTA 128x128, BK=32, 4-stage ring, 2 CTAs/SM, 8 warps (2m x 4n), warp 64x32.
// DUALA: A cols [0,256) from A, [256,512) from A2, both stride 256.
// EPI: 0 fp32, 2 relu + fp16, 3 qkv fp16 (elu+1 if col<512)
#define BM 128
#define BN 128
#define BK 32
#define TILEB 8192                   // one 128x32 fp16 tile (64B rows)
#define STG (2 * TILEB)              // A | B = 16384
#define NSTAGE 4
#define GSMEM (NSTAGE * STG)         // 65536 -> 2 CTAs/SM

// rows are 64B (32 fp16) wide, 4x16B chunks, swizzled
__device__ __forceinline__ uint32_t toff(int row, int c16) {
    return (uint32_t)(row * 64 + ((c16 ^ ((row >> 1) & 3)) << 4));
}

template <int EPI, bool DUALA>
__global__ __launch_bounds__(256, 2) void mmagemm(
    const __half* __restrict__ A, const __half* __restrict__ A2,
    const __half* __restrict__ B,
    float* __restrict__ Cf, __half* __restrict__ Ch,
    int Ndim, int Kdim)
{
    extern __shared__ char sraw[];
    const uint32_t sbase = smem_u32(sraw);

    const int tid = threadIdx.x;
    const int bm0 = blockIdx.y * BM, bn0 = blockIdx.x * BN;
    const int lane = tid & 31, warp = tid >> 5;
    const int wm = warp >> 2, wn = warp & 3;

    const int lrow = tid >> 2;            // 0..63
    const int lc16 = tid & 3;             // 16B chunk in 64B row

    // ldmatrix bases
    uint32_t aRB[4]; int aK3[4];
    const int khA = lane >> 4;            // 0/1
    #pragma unroll
    for (int mt = 0; mt < 4; mt++) {
        int row = wm * 64 + mt * 16 + (lane & 15);
        aRB[mt] = sbase + row * 64;
        aK3[mt] = (row >> 1) & 3;
    }
    uint32_t bRB[2]; int bK3[2];
    const int khB = (lane >> 3) & 1;
    #pragma unroll
    for (int g = 0; g < 2; g++) {
        int row = wn * 32 + g * 16 + ((lane >> 4) & 1) * 8 + (lane & 7);
        bRB[g] = sbase + TILEB + row * 64;
        bK3[g] = (row >> 1) & 3;
    }

    float acc[4][4][4];
    #pragma unroll
    for (int i = 0; i < 4; i++)
        #pragma unroll
        for (int j = 0; j < 4; j++)
            #pragma unroll
            for (int e = 0; e < 4; e++) acc[i][j][e] = 0.f;

    const int nk = Kdim / BK;

    auto load_stage = [&](int st, int kblk) {
        uint32_t sb = sbase + (uint32_t)st * STG;
        const __half* pA;
        int acol, astr;
        if (DUALA && kblk >= DMODEL) {
            pA = A2; acol = kblk - DMODEL; astr = DMODEL;
        } else {
            pA = A; acol = kblk; astr = DUALA ? DMODEL : Kdim;
        }
        #pragma unroll
        for (int i = 0; i < 2; i++) {
            int row = lrow + i * 64;
            uint32_t so = toff(row, lc16);
            size_t gA = (size_t)(bm0 + row) * astr + acol + lc16 * 8;
            size_t gB = (size_t)(bn0 + row) * Kdim + kblk + lc16 * 8;
            cpa(sb + so, pA + gA);
            cpa(sb + TILEB + so, B + gB);
        }
        cpa_commit();
    };

    load_stage(0, 0);
    load_stage(1, BK);
    load_stage(2, 2 * BK);

    for (int c = 0; c < nk; c++) {
        CPA_WAIT(NSTAGE - 2);
        __syncthreads();
        if (c + 3 < nk) load_stage((c + 3) % NSTAGE, (c + 3) * BK);
        else cpa_commit();

        uint32_t soff = (uint32_t)(c % NSTAGE) * STG;
        #pragma unroll
        for (int s = 0; s < 2; s++) {        // two k16 slabs in BK=32
            uint32_t a[4][4], bh[2][4];
            #pragma unroll
            for (int mt = 0; mt < 4; mt++)
                ldm_x4(a[mt], aRB[mt] + soff + (uint32_t)(((s * 2 + khA) ^ aK3[mt]) << 4));
            #pragma unroll
            for (int g = 0; g < 2; g++)
                ldm_x4(bh[g], bRB[g] + soff + (uint32_t)(((s * 2 + khB) ^ bK3[g]) << 4));
            #pragma unroll
            for (int mt = 0; mt < 4; mt++)
                #pragma unroll
                for (int nt = 0; nt < 4; nt++)
                    MMA(acc[mt][nt], a[mt], bh[nt >> 1][(nt & 1) * 2], bh[nt >> 1][(nt & 1) * 2 + 1]);
        }
    }

    // epilogue
    const bool qkv_act = (EPI == 3) && (bn0 < 2 * DMODEL);
    #pragma unroll
    for (int mt = 0; mt < 4; mt++) {
        #pragma unroll
        for (int nt = 0; nt < 4; nt++) {
            int row = bm0 + wm * 64 + mt * 16 + (lane >> 2);
            int col = bn0 + wn * 32 + nt * 8 + (lane & 3) * 2;
            float* a = acc[mt][nt];
            #pragma unroll
            for (int half = 0; half < 2; half++) {
                int r = row + half * 8;
                float v0 = a[half * 2], v1 = a[half * 2 + 1];
                size_t o = (size_t)r * Ndim + col;
                if (EPI == 0) {
                    float2 t = {v0, v1};
                    *(float2*)(Cf + o) = t;
                } else if (EPI == 3) {
                    if (qkv_act) {
                        v0 = v0 > 0.f ? v0 + 1.f : expf(v0);
                        v1 = v1 > 0.f ? v1 + 1.f : expf(v1);
                    }
                    __half2 p;
                    p.x = __float2half_rn(v0);
                    p.y = __float2half_rn(v1);
                    *(__half2*)(Ch + o) = p;
                } else {
                    v0 = v0 > 0.f ? v0 : 0.f;
                    v1 = v1 > 0.f ? v1 : 0.f;
                    __half2 p;
                    p.x = __float2half_rn(v0);
                    p.y = __float2half_rn(v1);
                    *(__half2*)(Ch + o) = p;
                }
            }
        }
    }
}

// ---------------- KV reduce phase 1 (32-row tiles, fp16 in) ----------------
__global__ __launch_bounds__(256) void kv_reduce1() {
    int blk = blockIdx.x;
    int sl = blk & 7, nh = blk >> 3;
    int n = nh >> 3, h = nh & 7;
    const __half* Kp = g_qkv + (size_t)n * LSEQ * QKVN + DMODEL + h * DHEAD;
    const __half* Vp = Kp + DMODEL;
    __shared__ float sK[32][32], sV[32][32];
    int tid = threadIdx.x;
    int d0 = tid >> 3, v0 = (tid & 7) * 4;
    int lrow = tid >> 3, lcol = (tid & 7) * 4;
    float a0 = 0, a1 = 0, a2 = 0, a3 = 0, ks = 0;
    int lbeg = sl * 512, lend = lbeg + 512;
    for (int l0 = lbeg; l0 < lend; l0 += 32) {
        size_t ro = (size_t)(l0 + lrow) * QKVN + lcol;
        {
            uint2 rk = *(const uint2*)(Kp + ro);
            float2 k01 = __half22float2(*(__half2*)&rk.x);
            float2 k23 = __half22float2(*(__half2*)&rk.y);
            sK[lrow][lcol + 0] = k01.x; sK[lrow][lcol + 1] = k01.y;
            sK[lrow][lcol + 2] = k23.x; sK[lrow][lcol + 3] = k23.y;
            uint2 rv = *(const uint2*)(Vp + ro);
            float2 v01 = __half22float2(*(__half2*)&rv.x);
            float2 v23 = __half22float2(*(__half2*)&rv.y);
            sV[lrow][lcol + 0] = v01.x; sV[lrow][lcol + 1] = v01.y;
            sV[lrow][lcol + 2] = v23.x; sV[lrow][lcol + 3] = v23.y;
        }
        __syncthreads();
        #pragma unroll
        for (int r = 0; r < 32; r++) {
            float kd = sK[r][d0];
            a0 += kd * sV[r][v0 + 0];
            a1 += kd * sV[r][v0 + 1];
            a2 += kd * sV[r][v0 + 2];
            a3 += kd * sV[r][v0 + 3];
            if ((tid & 7) == 0) ks += kd;
        }
        __syncthreads();
    }
    float* p = g_kvp + (size_t)blk * (DHEAD * DHEAD + DHEAD);
    float* kv = p + d0 * DHEAD + v0;
    kv[0] = a0; kv[1] = a1; kv[2] = a2; kv[3] = a3;
    if ((tid & 7) == 0) p[DHEAD * DHEAD + d0] = ks;
}

// ---------------- attention apply (reduces partials itself) ----------------
__global__ __launch_bounds__(256) void attn_apply() {
    int n = blockIdx.y, l0 = blockIdx.x * 128;
    __shared__ float sKV[NHEAD][DHEAD][DHEAD];
    __shared__ float sKs[NHEAD][DHEAD];
    int tid = threadIdx.x;
    const int PSTR = DHEAD * DHEAD + DHEAD;   // 1056
    const float* base = g_kvp + (size_t)n * NHEAD * 8 * PSTR;
    for (int i = tid; i < NHEAD * DHEAD * DHEAD; i += 256) {
        int h = i >> 10, e = i & 1023;
        float s = 0.f;
        #pragma unroll
        for (int p = 0; p < 8; p++) s += base[(size_t)(h * 8 + p) * PSTR + e];
        ((float*)sKV)[i] = s;
    }
    for (int i = tid; i < NHEAD * DHEAD; i += 256) {
        int h = i >> 5, e = i & 31;
        float s = 0.f;
        #pragma unroll
        for (int p = 0; p < 8; p++) s += base[(size_t)(h * 8 + p) * PSTR + 1024 + e];
        ((float*)sKs)[i] = s;
    }
    __syncthreads();
    #pragma unroll
    for (int p = 0; p < 4; p++) {
        int i = p * 256 + tid;
        int h = i >> 7, ll = i & 127;
        const __half* qp = g_qkv + ((size_t)n * LSEQ + l0 + ll) * QKVN + h * DHEAD;
        size_t rowo = ((size_t)n * LSEQ + l0 + ll) * DMODEL + h * DHEAD;
        float q[32];
        #pragma unroll
        for (int d = 0; d < 32; d += 8) {
            uint2 rq = *(const uint2*)(qp + d);
            float2 q01 = __half22float2(*(__half2*)&rq.x);
            float2 q23 = __half22float2(*(__half2*)&rq.y);
            q[d + 0] = q01.x; q[d + 1] = q01.y; q[d + 2] = q23.x; q[d + 3] = q23.y;
            uint2 rq2 = *(const uint2*)(qp + d + 4);
            float2 q45 = __half22float2(*(__half2*)&rq2.x);
            float2 q67 = __half22float2(*(__half2*)&rq2.y);
            q[d + 4] = q45.x; q[d + 5] = q45.y; q[d + 6] = q67.x; q[d + 7] = q67.y;
        }
        float zdot = 0.f;
        #pragma unroll
        for (int d = 0; d < 32; d++) zdot += q[d] * sKs[h][d];
        float z = 1.f / (zdot + 1e-6f);
        #pragma unroll
        for (int v = 0; v < 32; v += 2) {
            float b0 = 0.f, b1 = 0.f;
            #pragma unroll
            for (int d = 0; d < 32; d++) {
                float qq = q[d];
                b0 += qq * sKV[h][d][v];
                b1 += qq * sKV[h][d][v + 1];
            }
            __half2 ph;
            ph.x = __float2half_rn(b0 * z);
            ph.y = __float2half_rn(b1 * z);
            *(__half2*)(g_msgh + rowo + v) = ph;
        }
    }
}

// ---------------- LayerNorms ----------------
__global__ __launch_bounds__(256) void ln1(
    const float* __restrict__ inp, const float* __restrict__ gam, const float* __restrict__ bet)
{
    int row = blockIdx.x * 8 + (threadIdx.x >> 5);
    int lane = threadIdx.x & 31;
    const float* ip = inp + (size_t)row * DMODEL;
    float v[8]; float s = 0.f;
    #pragma unroll
    for (int j = 0; j < 8; j++) { v[j] = ip[lane + 32 * j]; s += v[j]; }
    s = warp_sum(s);
    float mu = s * (1.f / 256.f), s2 = 0.f;
    #pragma unroll
    for (int j = 0; j < 8; j++) { float d = v[j] - mu; s2 += d * d; }
    s2 = warp_sum(s2);
    float rs = rsqrtf(s2 * (1.f / 256.f) + 1e-5f);
    size_t co = (size_t)row * DMODEL;
    #pragma unroll
    for (int j = 0; j < 8; j++) {
        int c = lane + 32 * j;
        float lnv = (v[j] - mu) * rs * gam[c] + bet[c];
        g_lnh[co + c] = __float2half_rn(lnv);
    }
}
__global__ __launch_bounds__(256) void ln2_res(
    const float* __restrict__ inp, const float* __restrict__ gam, const float* __restrict__ bet)
{
    int row = blockIdx.x * 8 + (threadIdx.x >> 5);
    int lane = threadIdx.x & 31;
    const float* ip = inp + (size_t)row * DMODEL;
    float v[8]; float s = 0.f;
    #pragma unroll
    for (int j = 0; j < 8; j++) { v[j] = ip[lane + 32 * j]; s += v[j]; }
    s = warp_sum(s);
    float mu = s * (1.f / 256.f), s2 = 0.f;
    #pragma unroll
    for (int j = 0; j < 8; j++) { float d = v[j] - mu; s2 += d * d; }
    s2 = warp_sum(s2);
    float rs = rsqrtf(s2 * (1.f / 256.f) + 1e-5f);
    float* xp = g_x + (size_t)row * DMODEL;
    size_t xo = (size_t)row * DMODEL;
    #pragma unroll
    for (int j = 0; j < 8; j++) {
        int c = lane + 32 * j;
        float nx = xp[c] + (v[j] - mu) * rs * gam[c] + bet[c];
        xp[c] = nx;
        g_xh[xo + c] = __float2half_rn(nx);
    }
}

// ---------------- host ----------------
extern "C" void kernel_launch(void* const* d_in, const int* in_sizes, int n_in,
                              void* d_out, int out_size)
{
    const float* feats = (const float*)d_in[0];
    const float* Wq = (const float*)d_in[1];
    const float* Wk = (const float*)d_in[2];
    const float* Wv = (const float*)d_in[3];
    const float* Wm = (const float*)d_in[4];
    const float* W1 = (const float*)d_in[5];
    const float* W2 = (const float*)d_in[6];
    const float* ln1g = (const float*)d_in[7];
    const float* ln1b = (const float*)d_in[8];
    const float* ln2g = (const float*)d_in[9];
    const float* ln2b = (const float*)d_in[10];

    cudaFuncSetAttribute(mmagemm<0, false>, cudaFuncAttributeMaxDynamicSharedMemorySize, GSMEM);
    cudaFuncSetAttribute(mmagemm<2, true>,  cudaFuncAttributeMaxDynamicSharedMemorySize, GSMEM);
    cudaFuncSetAttribute(mmagemm<3, false>, cudaFuncAttributeMaxDynamicSharedMemorySize, GSMEM);

    float *px, *ptmp;
    __half *pqkv, *pxh, *pmh, *plh, *p1h, *pwh;
    cudaGetSymbolAddress((void**)&px, g_x);
    cudaGetSymbolAddress((void**)&ptmp, g_tmp);
    cudaGetSymbolAddress((void**)&pqkv, g_qkv);
    cudaGetSymbolAddress((void**)&pxh, g_xh);
    cudaGetSymbolAddress((void**)&pmh, g_msgh);
    cudaGetSymbolAddress((void**)&plh, g_lnh);
    cudaGetSymbolAddress((void**)&p1h, g_h1h);
    cudaGetSymbolAddress((void**)&pwh, g_wh);

    dim3 tb(32, 8);
    prep_weight<<<dim3(8, 8, NUM_LAYERS), tb>>>(Wq, pwh + OFF_Q, DMODEL, DMODEL, WSZ_D, WSZ_L);
    prep_weight<<<dim3(8, 8, NUM_LAYERS), tb>>>(Wk, pwh + OFF_K, DMODEL, DMODEL, WSZ_D, WSZ_L);
    prep_weight<<<dim3(8, 8, NUM_LAYERS), tb>>>(Wv, pwh + OFF_V, DMODEL, DMODEL, WSZ_D, WSZ_L);
    prep_weight<<<dim3(8, 8, NUM_LAYERS), tb>>>(Wm, pwh + OFF_M, DMODEL, DMODEL, WSZ_D, WSZ_L);
    prep_weight<<<dim3(16, 16, NUM_LAYERS), tb>>>(W1, pwh + OFF_1, 2 * DMODEL, 2 * DMODEL, 4 * WSZ_D, WSZ_L);
    prep_weight<<<dim3(8, 16, NUM_LAYERS), tb>>>(W2, pwh + OFF_2, 2 * DMODEL, DMODEL, 2 * WSZ_D, WSZ_L);

    add_pe_transpose<<<dim3(LSEQ / 32, DMODEL / 32, BATCH), tb>>>(feats);

    dim3 blk(256);
    dim3 grid_qkv(QKVN / BN, MROWS / BM);       // (6, 256)
    dim3 grid_d(DMODEL / BN, MROWS / BM);       // (2, 256)
    dim3 grid_2d(2 * DMODEL / BN, MROWS / BM);  // (4, 256)

    for (int i = 0; i < NUM_LAYERS; i++) {
        size_t wo = (size_t)i * WSZ_L;
        // fused QKV -> fp16 [elu(x@Wq)+1 | elu(x@Wk)+1 | x@Wv]
        mmagemm<3, false><<<grid_qkv, blk, GSMEM>>>(pxh, 0, pwh + wo + OFF_Q, 0, pqkv, QKVN, DMODEL);

        kv_reduce1<<<BATCH * NHEAD * 8, 256>>>();
        attn_apply<<<dim3(LSEQ / 128, BATCH), 256>>>();

        // merged = msg @ Wm -> g_tmp fp32
        mmagemm<0, false><<<grid_d, blk, GSMEM>>>(pmh, 0, pwh + wo + OFF_M, ptmp, 0, DMODEL, DMODEL);
        ln1<<<MROWS / 8, 256>>>(ptmp, ln1g + i * DMODEL, ln1b + i * DMODEL);

        // h1 = relu([x | LN] @ W1) -> fp16; h2 = h1 @ W2 -> g_tmp fp32
        mmagemm<2, true><<<grid_2d, blk, GSMEM>>>(pxh, plh, pwh + wo + OFF_1, 0, p1h, 2 * DMODEL, 2 * DMODEL);
        mmagemm<0, false><<<grid_d, blk, GSMEM>>>(p1h, 0, pwh + wo + OFF_2, ptmp, 0, DMODEL, 2 * DMODEL);

        ln2_res<<<MROWS / 8, 256>>>(ptmp, ln2g + i * DMODEL, ln2b + i * DMODEL);
    }

    transpose_out<<<dim3(LSEQ / 32, DMODEL / 32, BATCH), tb>>>((float*)d_out);
}

// round 14
// speedup vs baseline: 1.2194x; 1.0614x over previous
#include <cuda_runtime.h>
#include <cuda_fp16.h>
#include <math.h>
#include <cstdint>

#define BATCH 8
#define LSEQ  4096
#define DMODEL 256
#define NHEAD 8
#define DHEAD 32
#define MROWS (BATCH*LSEQ)
#define NUM_LAYERS 4
#define QKVN (3*DMODEL)   // 768

// ---------------- helpers ----------------
__device__ __forceinline__ uint32_t smem_u32(const void* p) {
    uint32_t a;
    asm("{ .reg .u64 t; cvta.to.shared.u64 t, %1; cvt.u32.u64 %0, t; }" : "=r"(a) : "l"(p));
    return a;
}
__device__ __forceinline__ void cpa(uint32_t s, const void* g) {
    asm volatile("cp.async.cg.shared.global [%0], [%1], 16;" :: "r"(s), "l"(g));
}
__device__ __forceinline__ void cpa8(uint32_t s, const void* g) {
    asm volatile("cp.async.ca.shared.global [%0], [%1], 8;" :: "r"(s), "l"(g));
}
__device__ __forceinline__ void cpa_commit() { asm volatile("cp.async.commit_group;" ::: "memory"); }
#define CPA_WAIT(n) asm volatile("cp.async.wait_group %0;" :: "n"(n) : "memory")
__device__ __forceinline__ void ldm_x4(uint32_t* r, uint32_t a) {
    asm volatile("ldmatrix.sync.aligned.m8n8.x4.shared.b16 {%0,%1,%2,%3}, [%4];"
        : "=r"(r[0]), "=r"(r[1]), "=r"(r[2]), "=r"(r[3]) : "r"(a));
}
#define MMA(c, a, b0v, b1v) \
    asm volatile("mma.sync.aligned.m16n8k16.row.col.f32.f16.f16.f32 " \
        "{%0,%1,%2,%3}, {%4,%5,%6,%7}, {%8,%9}, {%0,%1,%2,%3};" \
        : "+f"((c)[0]), "+f"((c)[1]), "+f"((c)[2]), "+f"((c)[3]) \
        : "r"((a)[0]), "r"((a)[1]), "r"((a)[2]), "r"((a)[3]), "r"(b0v), "r"(b1v))
__device__ __forceinline__ float warp_sum(float v) {
    #pragma unroll
    for (int o = 16; o > 0; o >>= 1) v += __shfl_xor_sync(0xffffffffu, v, o);
    return v;
}

// ---------------- scratch ----------------
__device__ float g_x[MROWS * DMODEL];
__device__ float g_tmp[MROWS * DMODEL];
__device__ float g_kv[BATCH * NHEAD * DHEAD * DHEAD];
__device__ float g_ksum[BATCH * NHEAD * DHEAD];
__device__ float g_kvp[BATCH * NHEAD * 8 * (DHEAD * DHEAD + DHEAD)];
__device__ __half g_qkv[MROWS * QKVN];
__device__ __half g_xh[MROWS * DMODEL];
__device__ __half g_msgh[MROWS * DMODEL];
__device__ __half g_lnh[MROWS * DMODEL];
__device__ __half g_h1h[MROWS * 2 * DMODEL];
__device__ __half g_wh[NUM_LAYERS * 10 * DMODEL * DMODEL];
#define WSZ_D (DMODEL * DMODEL)
#define WSZ_L (10 * WSZ_D)
#define OFF_Q 0
#define OFF_K (1 * WSZ_D)
#define OFF_V (2 * WSZ_D)
#define OFF_M (3 * WSZ_D)
#define OFF_1 (4 * WSZ_D)
#define OFF_2 (8 * WSZ_D)

// ---------------- PE + transposes ----------------
__device__ __forceinline__ float pe_val(int c, int l) {
    int i = c >> 2, m = c & 3;
    float pos = (m < 2) ? (float)((l & 63) + 1) : (float)((l >> 6) + 1);
    float dv = expf(-(float)(2 * i) * 0.07195578490697396f);
    float a = pos * dv;
    return (m & 1) ? cosf(a) : sinf(a);
}
__global__ void add_pe_transpose(const float* __restrict__ feats) {
    __shared__ float t[32][33];
    int b = blockIdx.z, c0 = blockIdx.y * 32, l0 = blockIdx.x * 32;
    int tx = threadIdx.x, ty = threadIdx.y;
    #pragma unroll
    for (int i = ty; i < 32; i += 8) {
        int c = c0 + i, l = l0 + tx;
        t[i][tx] = feats[((size_t)b * DMODEL + c) * LSEQ + l] + pe_val(c, l);
    }
    __syncthreads();
    #pragma unroll
    for (int i = ty; i < 32; i += 8) {
        int l = l0 + i, c = c0 + tx;
        float v = t[tx][i];
        size_t o = ((size_t)b * LSEQ + l) * DMODEL + c;
        g_x[o] = v;
        g_xh[o] = __float2half_rn(v);
    }
}
__global__ void transpose_out(float* __restrict__ out) {
    __shared__ float t[32][33];
    int b = blockIdx.z, c0 = blockIdx.y * 32, l0 = blockIdx.x * 32;
    int tx = threadIdx.x, ty = threadIdx.y;
    #pragma unroll
    for (int i = ty; i < 32; i += 8)
        t[i][tx] = g_x[((size_t)b * LSEQ + l0 + i) * DMODEL + c0 + tx];
    __syncthreads();
    #pragma unroll
    for (int i = ty; i < 32; i += 8)
        out[((size_t)b * DMODEL + c0 + i) * LSEQ + l0 + tx] = t[tx][i];
}

// W[K][N] fp32 -> [N][K] fp16
__global__ void prep_weight(const float* __restrict__ W, __half* __restrict__ Th,
                            int K, int N, int wstride, int ostride) {
    __shared__ float t[32][33];
    int L = blockIdx.z;
    const float* Wp = W + (size_t)L * wstride;
    int k0 = blockIdx.y * 32, n0 = blockIdx.x * 32;
    int tx = threadIdx.x, ty = threadIdx.y;
    #pragma unroll
    for (int i = ty; i < 32; i += 8)
        t[i][tx] = Wp[(size_t)(k0 + i) * N + n0 + tx];
    __syncthreads();
    #pragma unroll
    for (int i = ty; i < 32; i += 8) {
        float v = t[tx][i];
        size_t o = (size_t)L * ostride + (size_t)(n0 + i) * K + k0 + tx;
        Th[o] = __float2half_rn(v);
    }
}

// ---------------- mma.sync fp16 1-pass GEMM (R13 proven) ----------------
#define BM 128
#define BN 128
#define BK 32
#define TILEB 8192
#define STG (2 * TILEB)
#define NSTAGE 4
#define GSMEM (NSTAGE * STG)         // 65536 -> 2 CTAs/SM

__device__ __forceinline__ uint32_t toff(int row, int c16) {
    return (uint32_t)(row * 64 + ((c16 ^ ((row >> 1) & 3)) << 4));
}

template <int EPI, bool DUALA>
__global__ __launch_bounds__(256, 2) void mmagemm(
    const __half* __restrict__ A, const __half* __restrict__ A2,
    const __half* __restrict__ B,
    float* __restrict__ Cf, __half* __restrict__ Ch,
    int Ndim, int Kdim)
{
    extern __shared__ char sraw[];
    const uint32_t sbase = smem_u32(sraw);

    const int tid = threadIdx.x;
    const int bm0 = blockIdx.y * BM, bn0 = blockIdx.x * BN;
    const int lane = tid & 31, warp = tid >> 5;
    const int wm = warp >> 2, wn = warp & 3;

    const int lrow = tid >> 2;
    const int lc16 = tid & 3;

    uint32_t aRB[4]; int aK3[4];
    const int khA = lane >> 4;
    #pragma unroll
    for (int mt = 0; mt < 4; mt++) {
        int row = wm * 64 + mt * 16 + (lane & 15);
        aRB[mt] = sbase + row * 64;
        aK3[mt] = (row >> 1) & 3;
    }
    uint32_t bRB[2]; int bK3[2];
    const int khB = (lane >> 3) & 1;
    #pragma unroll
    for (int g = 0; g < 2; g++) {
        int row = wn * 32 + g * 16 + ((lane >> 4) & 1) * 8 + (lane & 7);
        bRB[g] = sbase + TILEB + row * 64;
        bK3[g] = (row >> 1) & 3;
    }

    float acc[4][4][4];
    #pragma unroll
    for (int i = 0; i < 4; i++)
        #pragma unroll
        for (int j = 0; j < 4; j++)
            #pragma unroll
            for (int e = 0; e < 4; e++) acc[i][j][e] = 0.f;

    const int nk = Kdim / BK;

    auto load_stage = [&](int st, int kblk) {
        uint32_t sb = sbase + (uint32_t)st * STG;
        const __half* pA;
        int acol, astr;
        if (DUALA && kblk >= DMODEL) {
            pA = A2; acol = kblk - DMODEL; astr = DMODEL;
        } else {
            pA = A; acol = kblk; astr = DUALA ? DMODEL : Kdim;
        }
        #pragma unroll
        for (int i = 0; i < 2; i++) {
            int row = lrow + i * 64;
            uint32_t so = toff(row, lc16);
            size_t gA = (size_t)(bm0 + row) * astr + acol + lc16 * 8;
            size_t gB = (size_t)(bn0 + row) * Kdim + kblk + lc16 * 8;
            cpa(sb + so, pA + gA);
            cpa(sb + TILEB + so, B + gB);
        }
        cpa_commit();
    };

    load_stage(0, 0);
    load_stage(1, BK);
    load_stage(2, 2 * BK);

    for (int c = 0; c < nk; c++) {
        CPA_WAIT(NSTAGE - 2);
        __syncthreads();
        if (c + 3 < nk) load_stage((c + 3) % NSTAGE, (c + 3) * BK);
        else cpa_commit();

        uint32_t soff = (uint32_t)(c % NSTAGE) * STG;
        #pragma unroll
        for (int s = 0; s < 2; s++) {
            uint32_t a[4][4], bh[2][4];
            #pragma unroll
            for (int mt = 0; mt < 4; mt++)
                ldm_x4(a[mt], aRB[mt] + soff + (uint32_t)(((s * 2 + khA) ^ aK3[mt]) << 4));
            #pragma unroll
            for (int g = 0; g < 2; g++)
                ldm_x4(bh[g], bRB[g] + soff + (uint32_t)(((s * 2 + khB) ^ bK3[g]) << 4));
            #pragma unroll
            for (int mt = 0; mt < 4; mt++)
                #pragma unroll
                for (int nt = 0; nt < 4; nt++)
                    MMA(acc[mt][nt], a[mt], bh[nt >> 1][(nt & 1) * 2], bh[nt >> 1][(nt & 1) * 2 + 1]);
        }
    }

    const bool qkv_act = (EPI == 3) && (bn0 < 2 * DMODEL);
    #pragma unroll
    for (int mt = 0; mt < 4; mt++) {
        #pragma unroll
        for (int nt = 0; nt < 4; nt++) {
            int row = bm0 + wm * 64 + mt * 16 + (lane >> 2);
            int col = bn0 + wn * 32 + nt * 8 + (lane & 3) * 2;
            float* a = acc[mt][nt];
            #pragma unroll
            for (int half = 0; half < 2; half++) {
                int r = row + half * 8;
                float v0 = a[half * 2], v1 = a[half * 2 + 1];
                size_t o = (size_t)r * Ndim + col;
                if (EPI == 0) {
                    float2 t = {v0, v1};
                    *(float2*)(Cf + o) = t;
                } else if (EPI == 3) {
                    if (qkv_act) {
                        v0 = v0 > 0.f ? v0 + 1.f : expf(v0);
                        v1 = v1 > 0.f ? v1 + 1.f : expf(v1);
                    }
                    __half2 p;
                    p.x = __float2half_rn(v0);
                    p.y = __float2half_rn(v1);
                    *(__half2*)(Ch + o) = p;
                } else {
                    v0 = v0 > 0.f ? v0 : 0.f;
                    v1 = v1 > 0.f ? v1 : 0.f;
                    __half2 p;
                    p.x = __float2half_rn(v0);
                    p.y = __float2half_rn(v1);
                    *(__half2*)(Ch + o) = p;
                }
            }
        }
    }
}

// ---------------- KV reduce phase 1: cp.async 3-stage ring ----------------
// grid 512 = (n,h,slice of 512 rows). fp16 tiles staged raw, one barrier/tile.
#define KVSTG 2048   // 32 rows x 32 halves = 2KB per tile

__global__ __launch_bounds__(256) void kv_reduce1() {
    __shared__ __half sK[3][32][32], sV[3][32][32];
    int blk = blockIdx.x;
    int sl = blk & 7, nh = blk >> 3;
    int n = nh >> 3, h = nh & 7;
    const __half* Kp = g_qkv + (size_t)n * LSEQ * QKVN + DMODEL + h * DHEAD;
    const __half* Vp = Kp + DMODEL;
    int tid = threadIdx.x;
    int d0 = tid >> 3, v0 = (tid & 7) * 4;
    int lrow = tid >> 3, lc8 = tid & 7;          // 8B chunk per thread
    uint32_t skb = smem_u32(&sK[0][0][0]);
    uint32_t svb = smem_u32(&sV[0][0][0]);
    uint32_t so = (uint32_t)(lrow * 64 + lc8 * 8);
    int lbeg = sl * 512;

    auto issue = [&](int t) {
        uint32_t st = (uint32_t)(t % 3) * KVSTG;
        size_t ro = (size_t)(lbeg + t * 32 + lrow) * QKVN + lc8 * 4;
        cpa8(skb + st + so, Kp + ro);
        cpa8(svb + st + so, Vp + ro);
        cpa_commit();
    };

    issue(0); issue(1);

    float a0 = 0, a1 = 0, a2 = 0, a3 = 0, ks = 0;
    for (int t = 0; t < 16; t++) {
        CPA_WAIT(1);
        __syncthreads();
        if (t + 2 < 16) issue(t + 2);
        else cpa_commit();
        int st = t % 3;
        #pragma unroll
        for (int r = 0; r < 32; r++) {
            float kd = __half2float(sK[st][r][d0]);
            float2 va = __half22float2(*(__half2*)&sV[st][r][v0]);
            float2 vb = __half22float2(*(__half2*)&sV[st][r][v0 + 2]);
            a0 += kd * va.x;
            a1 += kd * va.y;
            a2 += kd * vb.x;
            a3 += kd * vb.y;
            if ((tid & 7) == 0) ks += kd;
        }
    }
    float* p = g_kvp + (size_t)blk * (DHEAD * DHEAD + DHEAD);
    float* kv = p + d0 * DHEAD + v0;
    kv[0] = a0; kv[1] = a1; kv[2] = a2; kv[3] = a3;
    if ((tid & 7) == 0) p[DHEAD * DHEAD + d0] = ks;
}

// ---------------- KV reduce phase 2: sum 8 partials ----------------
__global__ __launch_bounds__(256) void kv_reduce2() {
    int nh = blockIdx.x, tid = threadIdx.x;
    const float* base = g_kvp + (size_t)nh * 8 * (DHEAD * DHEAD + DHEAD);
    #pragma unroll
    for (int ii = 0; ii < 4; ii++) {
        int i = ii * 256 + tid;
        float s = 0;
        #pragma unroll
        for (int p = 0; p < 8; p++) s += base[p * (DHEAD * DHEAD + DHEAD) + i];
        g_kv[(size_t)nh * DHEAD * DHEAD + i] = s;
    }
    if (tid < DHEAD) {
        float s = 0;
        #pragma unroll
        for (int p = 0; p < 8; p++) s += base[p * (DHEAD * DHEAD + DHEAD) + DHEAD * DHEAD + tid];
        g_ksum[(size_t)nh * DHEAD + tid] = s;
    }
}

// ---------------- attention apply: grid (32, 8, 4) ----------------
__global__ __launch_bounds__(256) void attn_apply() {
    int n = blockIdx.y, l0 = blockIdx.x * 128;
    __shared__ float sKV[NHEAD][DHEAD][DHEAD];
    __shared__ float sKs[NHEAD][DHEAD];
    int tid = threadIdx.x;
    const float* kvp = g_kv + (size_t)n * NHEAD * DHEAD * DHEAD;
    for (int i = tid; i < NHEAD * DHEAD * DHEAD; i += 256) ((float*)sKV)[i] = kvp[i];
    for (int i = tid; i < NHEAD * DHEAD; i += 256) ((float*)sKs)[i] = g_ksum[(size_t)n * NHEAD * DHEAD + i];
    __syncthreads();
    int i = blockIdx.z * 256 + tid;
    int h = i >> 7, ll = i & 127;
    const __half* qp = g_qkv + ((size_t)n * LSEQ + l0 + ll) * QKVN + h * DHEAD;
    size_t rowo = ((size_t)n * LSEQ + l0 + ll) * DMODEL + h * DHEAD;
    float q[32];
    #pragma unroll
    for (int d = 0; d < 32; d += 8) {
        uint2 rq = *(const uint2*)(qp + d);
        float2 q01 = __half22float2(*(__half2*)&rq.x);
        float2 q23 = __half22float2(*(__half2*)&rq.y);
        q[d + 0] = q01.x; q[d + 1] = q01.y; q[d + 2] = q23.x; q[d + 3] = q23.y;
        uint2 rq2 = *(const uint2*)(qp + d + 4);
        float2 q45 = __half22float2(*(__half2*)&rq2.x);
        float2 q67 = __half22float2(*(__half2*)&rq2.y);
        q[d + 4] = q45.x; q[d + 5] = q45.y; q[d + 6] = q67.x; q[d + 7] = q67.y;
    }
    float zdot = 0.f;
    #pragma unroll
    for (int d = 0; d < 32; d++) zdot += q[d] * sKs[h][d];
    float z = 1.f / (zdot + 1e-6f);
    #pragma unroll
    for (int v = 0; v < 32; v += 2) {
        float b0 = 0.f, b1 = 0.f;
        #pragma unroll
        for (int d = 0; d < 32; d++) {
            float qq = q[d];
            b0 += qq * sKV[h][d][v];
            b1 += qq * sKV[h][d][v + 1];
        }
        __half2 ph;
        ph.x = __float2half_rn(b0 * z);
        ph.y = __float2half_rn(b1 * z);
        *(__half2*)(g_msgh + rowo + v) = ph;
    }
}

// ---------------- LayerNorms ----------------
__global__ __launch_bounds__(256) void ln1(
    const float* __restrict__ inp, const float* __restrict__ gam, const float* __restrict__ bet)
{
    int row = blockIdx.x * 8 + (threadIdx.x >> 5);
    int lane = threadIdx.x & 31;
    const float* ip = inp + (size_t)row * DMODEL;
    float v[8]; float s = 0.f;
    #pragma unroll
    for (int j = 0; j < 8; j++) { v[j] = ip[lane + 32 * j]; s += v[j]; }
    s = warp_sum(s);
    float mu = s * (1.f / 256.f), s2 = 0.f;
    #pragma unroll
    for (int j = 0; j < 8; j++) { float d = v[j] - mu; s2 += d * d; }
    s2 = warp_sum(s2);
    float rs = rsqrtf(s2 * (1.f / 256.f) + 1e-5f);
    size_t co = (size_t)row * DMODEL;
    #pragma unroll
    for (int j = 0; j < 8; j++) {
        int c = lane + 32 * j;
        float lnv = (v[j] - mu) * rs * gam[c] + bet[c];
        g_lnh[co + c] = __float2half_rn(lnv);
    }
}
__global__ __launch_bounds__(256) void ln2_res(
    const float* __restrict__ inp, const float* __restrict__ gam, const float* __restrict__ bet)
{
    int row = blockIdx.x * 8 + (threadIdx.x >> 5);
    int lane = threadIdx.x & 31;
    const float* ip = inp + (size_t)row * DMODEL;
    float v[8]; float s = 0.f;
    #pragma unroll
    for (int j = 0; j < 8; j++) { v[j] = ip[lane + 32 * j]; s += v[j]; }
    s = warp_sum(s);
    float mu = s * (1.f / 256.f), s2 = 0.f;
    #pragma unroll
    for (int j = 0; j < 8; j++) { float d = v[j] - mu; s2 += d * d; }
    s2 = warp_sum(s2);
    float rs = rsqrtf(s2 * (1.f / 256.f) + 1e-5f);
    float* xp = g_x + (size_t)row * DMODEL;
    size_t xo = (size_t)row * DMODEL;
    #pragma unroll
    for (int j = 0; j < 8; j++) {
        int c = lane + 32 * j;
        float nx = xp[c] + (v[j] - mu) * rs * gam[c] + bet[c];
        xp[c] = nx;
        g_xh[xo + c] = __float2half_rn(nx);
    }
}

// ---------------- host ----------------
extern "C" void kernel_launch(void* const* d_in, const int* in_sizes, int n_in,
                              void* d_out, int out_size)
{
    const float* feats = (const float*)d_in[0];
    const float* Wq = (const float*)d_in[1];
    const float* Wk = (const float*)d_in[2];
    const float* Wv = (const float*)d_in[3];
    const float* Wm = (const float*)d_in[4];
    const float* W1 = (const float*)d_in[5];
    const float* W2 = (const float*)d_in[6];
    const float* ln1g = (const float*)d_in[7];
    const float* ln1b = (const float*)d_in[8];
    const float* ln2g = (const float*)d_in[9];
    const float* ln2b = (const float*)d_in[10];

    cudaFuncSetAttribute(mmagemm<0, false>, cudaFuncAttributeMaxDynamicSharedMemorySize, GSMEM);
    cudaFuncSetAttribute(mmagemm<2, true>,  cudaFuncAttributeMaxDynamicSharedMemorySize, GSMEM);
    cudaFuncSetAttribute(mmagemm<3, false>, cudaFuncAttributeMaxDynamicSharedMemorySize, GSMEM);

    float *px, *ptmp;
    __half *pqkv, *pxh, *pmh, *plh, *p1h, *pwh;
    cudaGetSymbolAddress((void**)&px, g_x);
    cudaGetSymbolAddress((void**)&ptmp, g_tmp);
    cudaGetSymbolAddress((void**)&pqkv, g_qkv);
    cudaGetSymbolAddress((void**)&pxh, g_xh);
    cudaGetSymbolAddress((void**)&pmh, g_msgh);
    cudaGetSymbolAddress((void**)&plh, g_lnh);
    cudaGetSymbolAddress((void**)&p1h, g_h1h);
    cudaGetSymbolAddress((void**)&pwh, g_wh);

    dim3 tb(32, 8);
    prep_weight<<<dim3(8, 8, NUM_LAYERS), tb>>>(Wq, pwh + OFF_Q, DMODEL, DMODEL, WSZ_D, WSZ_L);
    prep_weight<<<dim3(8, 8, NUM_LAYERS), tb>>>(Wk, pwh + OFF_K, DMODEL, DMODEL, WSZ_D, WSZ_L);
    prep_weight<<<dim3(8, 8, NUM_LAYERS), tb>>>(Wv, pwh + OFF_V, DMODEL, DMODEL, WSZ_D, WSZ_L);
    prep_weight<<<dim3(8, 8, NUM_LAYERS), tb>>>(Wm, pwh + OFF_M, DMODEL, DMODEL, WSZ_D, WSZ_L);
    prep_weight<<<dim3(16, 16, NUM_LAYERS), tb>>>(W1, pwh + OFF_1, 2 * DMODEL, 2 * DMODEL, 4 * WSZ_D, WSZ_L);
    prep_weight<<<dim3(8, 16, NUM_LAYERS), tb>>>(W2, pwh + OFF_2, 2 * DMODEL, DMODEL, 2 * WSZ_D, WSZ_L);

    add_pe_transpose<<<dim3(LSEQ / 32, DMODEL / 32, BATCH), tb>>>(feats);

    dim3 blk(256);
    dim3 grid_qkv(QKVN / BN, MROWS / BM);       // (6, 256)
    dim3 grid_d(DMODEL / BN, MROWS / BM);       // (2, 256)
    dim3 grid_2d(2 * DMODEL / BN, MROWS / BM);  // (4, 256)

    for (int i = 0; i < NUM_LAYERS; i++) {
        size_t wo = (size_t)i * WSZ_L;
        // fused QKV -> fp16 [elu(x@Wq)+1 | elu(x@Wk)+1 | x@Wv]
        mmagemm<3, false><<<grid_qkv, blk, GSMEM>>>(pxh, 0, pwh + wo + OFF_Q, 0, pqkv, QKVN, DMODEL);

        kv_reduce1<<<BATCH * NHEAD * 8, 256>>>();
        kv_reduce2<<<BATCH * NHEAD, 256>>>();
        attn_apply<<<dim3(LSEQ / 128, BATCH, 4), 256>>>();

        // merged = msg @ Wm -> g_tmp fp32
        mmagemm<0, false><<<grid_d, blk, GSMEM>>>(pmh, 0, pwh + wo + OFF_M, ptmp, 0, DMODEL, DMODEL);
        ln1<<<MROWS / 8, 256>>>(ptmp, ln1g + i * DMODEL, ln1b + i * DMODEL);

        // h1 = relu([x | LN] @ W1) -> fp16; h2 = h1 @ W2 -> g_tmp fp32
        mmagemm<2, true><<<grid_2d, blk, GSMEM>>>(pxh, plh, pwh + wo + OFF_1, 0, p1h, 2 * DMODEL, 2 * DMODEL);
        mmagemm<0, false><<<grid_d, blk, GSMEM>>>(p1h, 0, pwh + wo + OFF_2, ptmp, 0, DMODEL, 2 * DMODEL);

        ln2_res<<<MROWS / 8, 256>>>(ptmp, ln2g + i * DMODEL, ln2b + i * DMODEL);
    }

    transpose_out<<<dim3(LSEQ / 32, DMODEL / 32, BATCH), tb>>>((float*)d_out);
}